// round 14
// baseline (speedup 1.0000x reference)
#include <cuda_runtime.h>
#include <cuda_fp16.h>
#include <math.h>
#include <stdint.h>
#include <stddef.h>

#define B_ 16
#define C_ 512
#define N_ 4096
#define NROWS (B_*C_)

#define TM 128
#define TN 128
#define TKC 32
#define NTHREADS 256                      // 8 warps, 2M x 4N, warp tile 64x32

#define A_PAD 40
#define B_PAD_T 136
#define TILEA_H 5120                      // 128*40 halves
#define TILEB_H 4352                      // 32*136 halves
#define TILEA_BYTES 10240
#define TILEB_BYTES 8704

#define AH_BYTES 10240
#define STG_BYTES 20480
#define NSTAGE 4
#define SMEM_TILES 1024
#define SMEM_TOTAL (SMEM_TILES + NSTAGE*STG_BYTES)   // 82944, 2 CTAs/SM

// batch strides (halves)
#define QKVRM_B  ((size_t)1024*4096)
#define BMN_B    ((size_t)32*16*TILEB_H)
#define AFMT_BIG ((size_t)4*128*TILEA_H)
#define AFMT_AT  ((size_t)4*16*TILEA_H)
#define RM_B     ((size_t)C_*N_)

// ---------------- scratch ----------------
__device__ __half g_qkvRM[(size_t)B_*QKVRM_B];
__device__ __half g_vhT [(size_t)B_*BMN_B];
__device__ __half g_xhT [(size_t)B_*BMN_B];
__device__ __half g_yhT [(size_t)B_*BMN_B];
__device__ __half g_sq  [(size_t)B_*AFMT_BIG];
__device__ __half g_kh  [(size_t)B_*AFMT_BIG];
__device__ __half g_qh  [(size_t)B_*AFMT_BIG];
__device__ __half g_at  [(size_t)B_*AFMT_AT];
__device__ __half g_yhR [(size_t)B_*RM_B];
__device__ __half g_gph [(size_t)B_*RM_B];
__device__ __half g_wqkvT[12*16*TILEA_H];
__device__ __half g_wmT  [ 8*16*TILEA_H];
__device__ __half g_wgT  [ 4*32*TILEA_H];
__device__ __half g_wrT  [ 4*16*TILEA_H];

// ---------------- PTX helpers ----------------
__device__ __forceinline__ uint32_t smem_u32(const void* p){
    uint32_t a;
    asm("{ .reg .u64 t; cvta.to.shared.u64 t, %1; cvt.u32.u64 %0, t; }"
        : "=r"(a) : "l"(p));
    return a;
}
__device__ __forceinline__ void bulk_g2s(uint32_t dst, const void* src,
                                         uint32_t bytes, uint32_t bar){
    asm volatile(
        "cp.async.bulk.shared::cta.global.mbarrier::complete_tx::bytes "
        "[%0], [%1], %2, [%3];"
        :: "r"(dst), "l"(src), "r"(bytes), "r"(bar) : "memory");
}
__device__ __forceinline__ void mbar_init(uint32_t a, uint32_t n){
    asm volatile("mbarrier.init.shared.b64 [%0], %1;" :: "r"(a), "r"(n) : "memory");
}
__device__ __forceinline__ void mbar_expect(uint32_t a, uint32_t bytes){
    asm volatile("mbarrier.arrive.expect_tx.shared.b64 _, [%0], %1;"
                 :: "r"(a), "r"(bytes) : "memory");
}
__device__ __forceinline__ void mbar_wait(uint32_t a, uint32_t parity){
    asm volatile(
        "{\n\t.reg .pred P;\n\tWAITL%=:\n\t"
        "mbarrier.try_wait.parity.shared.b64 P, [%0], %1;\n\t"
        "@!P bra WAITL%=;\n\t}"
        :: "r"(a), "r"(parity) : "memory");
}
__device__ __forceinline__ void ldsm4(uint32_t* r, uint32_t addr){
    asm volatile("ldmatrix.sync.aligned.m8n8.x4.shared.b16 {%0,%1,%2,%3}, [%4];"
        : "=r"(r[0]), "=r"(r[1]), "=r"(r[2]), "=r"(r[3]) : "r"(addr));
}
__device__ __forceinline__ void ldsm4t(uint32_t* r, uint32_t addr){
    asm volatile("ldmatrix.sync.aligned.m8n8.x4.trans.shared.b16 {%0,%1,%2,%3}, [%4];"
        : "=r"(r[0]), "=r"(r[1]), "=r"(r[2]), "=r"(r[3]) : "r"(addr));
}
__device__ __forceinline__ void mma16816(float* c, const uint32_t* a, const uint32_t* b){
    asm volatile(
        "mma.sync.aligned.m16n8k16.row.col.f32.f16.f16.f32 "
        "{%0,%1,%2,%3}, {%4,%5,%6,%7}, {%8,%9}, {%0,%1,%2,%3};"
        : "+f"(c[0]), "+f"(c[1]), "+f"(c[2]), "+f"(c[3])
        : "r"(a[0]), "r"(a[1]), "r"(a[2]), "r"(a[3]), "r"(b[0]), "r"(b[1]));
}
__device__ __forceinline__ uint32_t pack_h2(float x, float y){
    __half2 p(__float2half_rn(x), __float2half_rn(y));
    return *(uint32_t*)&p;
}
__device__ __forceinline__ float2 unpack_h2(uint32_t u){
    __half2 p = *(__half2*)&u;
    return make_float2(__half2float(p.x), __half2float(p.y));
}

// ---------------------------------------------------------------------------
// fp16 GEMM, bulk-copy pipeline. CTA 128x128, 8 warps (2Mx4N), warp 64x32.
// modes: 0 scores / 1 final / 2 mqk / 3 qkv / 4 y / 5 gate
// ---------------------------------------------------------------------------
__global__ void __launch_bounds__(NTHREADS, 2) mma_gemm(
    const __half* __restrict__ A, int aNC, size_t aTB,
    const __half* __restrict__ B1, int b1NC, size_t b1TB,
    const __half* __restrict__ B2, int b2NC, size_t b2TB, int K1c,
    const float* __restrict__ bias, float scale,
    float* __restrict__ Y32,
    __half* __restrict__ O1, __half* __restrict__ O2,
    const __half* __restrict__ E1, const __half* __restrict__ E2,
    int NC, int transB, int mode)
{
    extern __shared__ char smem[];
    const uint32_t sbase = smem_u32(smem);
    const uint32_t tiles = sbase + SMEM_TILES;

    const int tid  = threadIdx.x;
    const int lane = tid & 31;
    const int wid  = tid >> 5;       // 0..7
    const int wm   = wid & 1;        // M strip of 64
    const int wn   = wid >> 1;       // N strip of 32 (0..3)
    const int b    = blockIdx.z;
    const int m0   = blockIdx.y * TM;
    const int n0   = blockIdx.x * TN;

    const __half* Ab  = A  + (size_t)b * aTB;
    const __half* B1b = B1 + (size_t)b * b1TB;
    const __half* B2b = B2 ? (B2 + (size_t)b * b2TB) : (const __half*)0;

    const uint32_t expect = TILEA_BYTES + (transB ? TILEB_BYTES : TILEA_BYTES);

    if (tid == 0){
        #pragma unroll
        for (int s = 0; s < NSTAGE; s++) mbar_init(sbase + s*8, 1);
    }

    auto issue = [&](int kc){
        const int s = kc & 3;
        const uint32_t bar = sbase + s*8;
        mbar_expect(bar, expect);
        const __half* srcA = Ab + ((size_t)(m0 >> 7) * aNC + kc) * TILEA_H;
        bulk_g2s(tiles + s*STG_BYTES, srcA, TILEA_BYTES, bar);
        if (transB){
            const __half* srcB = (kc < K1c)
                ? B1b + ((size_t)(n0 >> 7) * b1NC + kc) * TILEB_H
                : B2b + ((size_t)(n0 >> 7) * b2NC + (kc - K1c)) * TILEB_H;
            bulk_g2s(tiles + s*STG_BYTES + AH_BYTES, srcB, TILEB_BYTES, bar);
        } else {
            const __half* srcB = B1b + ((size_t)(n0 >> 7) * b1NC + kc) * TILEA_H;
            bulk_g2s(tiles + s*STG_BYTES + AH_BYTES, srcB, TILEA_BYTES, bar);
        }
    };

    if (tid == 0){
        issue(0);
        if (NC > 1) issue(1);
        if (NC > 2) issue(2);
    }
    __syncthreads();

    float acc[4][4][4];
    #pragma unroll
    for (int i = 0; i < 4; i++)
        #pragma unroll
        for (int j = 0; j < 4; j++)
            #pragma unroll
            for (int r = 0; r < 4; r++) acc[i][j][r] = 0.f;

    const int a_lrow = lane & 15;
    const int a_lcol = (lane >> 4) << 3;
    const int i4 = lane >> 3;
    const int r8 = lane & 7;
    const int kt = lane & 15;
    const int nh = lane >> 4;

    for (int kc = 0; kc < NC; kc++){
        mbar_wait(sbase + (kc & 3)*8, (kc >> 2) & 1);
        __syncthreads();

        const uint32_t sa = tiles + (kc & 3) * STG_BYTES;
        const uint32_t sb = sa + AH_BYTES;

        #pragma unroll
        for (int ks = 0; ks < 2; ks++){
            uint32_t ah[4][4], bb[4][2];
            #pragma unroll
            for (int mt = 0; mt < 4; mt++){
                uint32_t ad = sa + 2 * ((wm*64 + mt*16 + a_lrow) * A_PAD + ks*16 + a_lcol);
                ldsm4(ah[mt], ad);
            }
            #pragma unroll
            for (int p = 0; p < 2; p++){
                uint32_t r4[4];
                if (transB){
                    uint32_t bd = sb + 2 * ((ks*16 + kt) * B_PAD_T + wn*32 + (2*p + nh)*8);
                    ldsm4t(r4, bd);
                } else {
                    int row = wn*32 + (2*p + (i4 >> 1))*8 + r8;
                    int col = ks*16 + (i4 & 1)*8;
                    ldsm4(r4, sb + 2 * (row * A_PAD + col));
                }
                bb[2*p][0]   = r4[0];
                bb[2*p][1]   = r4[1];
                bb[2*p+1][0] = r4[2];
                bb[2*p+1][1] = r4[3];
            }
            #pragma unroll
            for (int mt = 0; mt < 4; mt++)
                #pragma unroll
                for (int nt = 0; nt < 4; nt++)
                    mma16816(acc[mt][nt], ah[mt], bb[nt]);
        }

        if (tid == 0 && kc + 3 < NC) issue(kc + 3);
    }

    // ---- epilogue ----
    const int g = lane >> 2;
    const int t = lane & 3;
    #pragma unroll
    for (int mt = 0; mt < 4; mt++){
        int m = m0 + wm*64 + mt*16 + g;
        float bi_lo = bias ? bias[m]     : 0.f;
        float bi_hi = bias ? bias[m + 8] : 0.f;
        #pragma unroll
        for (int nt = 0; nt < 4; nt++){
            int nn = n0 + wn*32 + nt*8 + 2*t;
            float v00 = acc[mt][nt][0] * scale + bi_lo;
            float v01 = acc[mt][nt][1] * scale + bi_lo;
            float v10 = acc[mt][nt][2] * scale + bi_hi;
            float v11 = acc[mt][nt][3] * scale + bi_hi;

            if (mode == 0){
                size_t off0 = (size_t)b*((size_t)C_*C_) + (size_t)m*C_ + nn;
                size_t off1 = off0 + (size_t)8*C_;
                float2 o0 = {v00, v01}, o1 = {v10, v11};
                *(float2*)(Y32 + off0) = o0;
                *(float2*)(Y32 + off1) = o1;
            } else if (mode == 3){
                if (m < 1024){
                    size_t o0 = (size_t)b*QKVRM_B + (size_t)m*N_ + nn;
                    *(uint32_t*)(O1 + o0)                = pack_h2(v00, v01);
                    *(uint32_t*)(O1 + o0 + 8*(size_t)N_) = pack_h2(v10, v11);
                } else {
                    int c = m - 1024;
                    size_t base = (size_t)b*BMN_B
                        + ((size_t)(nn>>7)*16 + (c>>5))*TILEB_H + (nn & 127);
                    *(uint32_t*)(O2 + base + (size_t)(c & 31)*B_PAD_T)       = pack_h2(v00, v01);
                    *(uint32_t*)(O2 + base + (size_t)((c & 31) + 8)*B_PAD_T) = pack_h2(v10, v11);
                }
            } else if (mode == 2){
                size_t eo = (size_t)b*QKVRM_B + (size_t)m*N_ + nn;
                float2 q0 = unpack_h2(*(const uint32_t*)(E1 + eo));
                float2 q1 = unpack_h2(*(const uint32_t*)(E1 + eo + 8*(size_t)N_));
                float p00 = v00*q0.x, p01 = v01*q0.y, p10 = v10*q1.x, p11 = v11*q1.y;
                bool neg = (m < 512);
                p00 = neg ? -fmaxf(p00,0.f) : fmaxf(p00,0.f);
                p01 = neg ? -fmaxf(p01,0.f) : fmaxf(p01,0.f);
                p10 = neg ? -fmaxf(p10,0.f) : fmaxf(p10,0.f);
                p11 = neg ? -fmaxf(p11,0.f) : fmaxf(p11,0.f);
                __half* dst = neg ? O1 : O2;
                int mm = neg ? m : (m - 512);
                size_t base = (size_t)b*AFMT_BIG
                    + ((size_t)(mm>>7)*128 + (nn>>5))*TILEA_H + (nn & 31);
                *(uint32_t*)(dst + base + (size_t)(mm & 127)*A_PAD)       = pack_h2(p00, p01);
                *(uint32_t*)(dst + base + (size_t)((mm & 127) + 8)*A_PAD) = pack_h2(p10, p11);
            } else if (mode == 4){
                size_t bt = (size_t)b*BMN_B
                    + ((size_t)(nn>>7)*16 + (m>>5))*TILEB_H + (nn & 127);
                *(uint32_t*)(O1 + bt + (size_t)(m & 31)*B_PAD_T)       = pack_h2(v00, v01);
                *(uint32_t*)(O1 + bt + (size_t)((m & 31) + 8)*B_PAD_T) = pack_h2(v10, v11);
                size_t o0 = (size_t)b*RM_B + (size_t)m*N_ + nn;
                *(uint32_t*)(O2 + o0)                = pack_h2(v00, v01);
                *(uint32_t*)(O2 + o0 + 8*(size_t)N_) = pack_h2(v10, v11);
            } else if (mode == 5){
                size_t o0 = (size_t)b*RM_B + (size_t)m*N_ + nn;
                *(uint32_t*)(O1 + o0)                = pack_h2(v00, v01);
                *(uint32_t*)(O1 + o0 + 8*(size_t)N_) = pack_h2(v10, v11);
            } else {
                size_t eo0 = (size_t)b*RM_B + (size_t)m*N_ + nn;
                size_t eo1 = eo0 + 8*(size_t)N_;
                float2 gp0 = unpack_h2(*(const uint32_t*)(E1 + eo0));
                float2 gp1 = unpack_h2(*(const uint32_t*)(E1 + eo1));
                float2 y0  = unpack_h2(*(const uint32_t*)(E2 + eo0));
                float2 y1  = unpack_h2(*(const uint32_t*)(E2 + eo1));
                float s0 = 1.f/(1.f+__expf(-gp0.x));
                float s1 = 1.f/(1.f+__expf(-gp0.y));
                float s2 = 1.f/(1.f+__expf(-gp1.x));
                float s3 = 1.f/(1.f+__expf(-gp1.y));
                size_t off0 = (size_t)b*RM_B + (size_t)m*N_ + nn;
                size_t off1 = off0 + 8*(size_t)N_;
                float2 o0, o1;
                o0.x = y0.x + s0*(v00 - y0.x);
                o0.y = y0.y + s1*(v01 - y0.y);
                o1.x = y1.x + s2*(v10 - y1.x);
                o1.y = y1.y + s3*(v11 - y1.y);
                *(float2*)(Y32 + off0) = o0;
                *(float2*)(Y32 + off1) = o1;
            }
        }
    }
}

// ---------------------------------------------------------------------------
__global__ void retile_w(const float* __restrict__ s, __half* __restrict__ d,
                         int M, int K)
{
    int i = blockIdx.x * 256 + threadIdx.x;
    if (i >= M*K) return;
    int m = i / K, k = i % K;
    size_t o = ((size_t)(m>>7)*(K>>5) + (k>>5))*TILEA_H + (size_t)(m & 127)*A_PAD + (k & 31);
    d[o] = __float2half_rn(s[i]);
}
__global__ void retile_x(const float* __restrict__ s, __half* __restrict__ d)
{
    int i = blockIdx.x * 256 + threadIdx.x;
    if (i >= B_*C_*N_) return;
    int b = i / (C_*N_);
    int rem = i - b*(C_*N_);
    int c = rem >> 12, pos = rem & 4095;
    size_t o = (size_t)b*BMN_B + ((size_t)(pos>>7)*16 + (c>>5))*TILEB_H
             + (size_t)(c & 31)*B_PAD_T + (pos & 127);
    d[o] = __float2half_rn(s[i]);
}

// ---------------------------------------------------------------------------
__global__ void softmax_q(const __half* __restrict__ sq, __half* __restrict__ qh)
{
    __shared__ float red[8];
    __shared__ float bc;
    const int row = blockIdx.x;
    const int b = row >> 9, c = row & 511;
    const size_t tb = (size_t)b*AFMT_BIG + (size_t)(c>>7)*128*TILEA_H
                    + (size_t)(c & 127)*A_PAD;

    float v[16];
    float mx = -1e30f;
    #pragma unroll
    for (int i = 0; i < 8; i++){
        int hidx = threadIdx.x + (i << 8);
        int n = hidx << 1;
        size_t off = tb + (size_t)(n>>5)*TILEA_H + (n & 31);
        float2 f = unpack_h2(*(const uint32_t*)(sq + off));
        v[2*i] = f.x; v[2*i+1] = f.y;
        mx = fmaxf(mx, fmaxf(f.x, f.y));
    }
    #pragma unroll
    for (int off = 16; off; off >>= 1)
        mx = fmaxf(mx, __shfl_xor_sync(0xffffffffu, mx, off));
    if ((threadIdx.x & 31) == 0) red[threadIdx.x >> 5] = mx;
    __syncthreads();
    if (threadIdx.x == 0){
        float tv = red[0];
        #pragma unroll
        for (int i = 1; i < 8; i++) tv = fmaxf(tv, red[i]);
        bc = tv;
    }
    __syncthreads();
    mx = bc;

    float sm = 0.f;
    #pragma unroll
    for (int i = 0; i < 16; i++){
        v[i] = __expf(v[i] - mx);
        sm += v[i];
    }
    #pragma unroll
    for (int off = 16; off; off >>= 1)
        sm += __shfl_xor_sync(0xffffffffu, sm, off);
    __syncthreads();
    if ((threadIdx.x & 31) == 0) red[threadIdx.x >> 5] = sm;
    __syncthreads();
    if (threadIdx.x == 0){
        float tv = 0.f;
        #pragma unroll
        for (int i = 0; i < 8; i++) tv += red[i];
        bc = tv;
    }
    __syncthreads();
    const float rinv = 1.f / bc;
    #pragma unroll
    for (int i = 0; i < 8; i++){
        int hidx = threadIdx.x + (i << 8);
        int n = hidx << 1;
        size_t off = tb + (size_t)(n>>5)*TILEA_H + (n & 31);
        *(uint32_t*)(qh + off) = pack_h2(v[2*i]*rinv, v[2*i+1]*rinv);
    }
}

// ---------------------------------------------------------------------------
__global__ void softmax_attn(float* __restrict__ S, __half* __restrict__ at)
{
    __shared__ float red[4];
    __shared__ float bc;
    const int row = blockIdx.x;
    const int b = row >> 9, c = row & 511;
    float* p = S + (size_t)row * 512;
    const size_t tb = (size_t)b*AFMT_AT + (size_t)(c>>7)*16*TILEA_H
                    + (size_t)(c & 127)*A_PAD;

    float v[4];
    float mx = -1e30f;
    #pragma unroll
    for (int i = 0; i < 4; i++){
        int idx = threadIdx.x + (i << 7);
        v[i] = p[idx];
        mx = fmaxf(mx, v[i]);
    }
    #pragma unroll
    for (int off = 16; off; off >>= 1)
        mx = fmaxf(mx, __shfl_xor_sync(0xffffffffu, mx, off));
    if ((threadIdx.x & 31) == 0) red[threadIdx.x >> 5] = mx;
    __syncthreads();
    if (threadIdx.x == 0)
        bc = fmaxf(fmaxf(red[0], red[1]), fmaxf(red[2], red[3]));
    __syncthreads();
    mx = bc;

    float sm = 0.f;
    #pragma unroll
    for (int i = 0; i < 4; i++){
        v[i] = __expf(v[i] - mx);
        sm += v[i];
    }
    #pragma unroll
    for (int off = 16; off; off >>= 1)
        sm += __shfl_xor_sync(0xffffffffu, sm, off);
    __syncthreads();
    if ((threadIdx.x & 31) == 0) red[threadIdx.x >> 5] = sm;
    __syncthreads();
    if (threadIdx.x == 0) bc = red[0] + red[1] + red[2] + red[3];
    __syncthreads();
    const float rinv = 1.f / bc;
    #pragma unroll
    for (int i = 0; i < 4; i++){
        int d = threadIdx.x + (i << 7);
        float f = v[i] * rinv;
        p[d] = f;
        at[tb + (size_t)(d>>5)*TILEA_H + (d & 31)] = __float2half_rn(f);
    }
}

// ---------------------------------------------------------------------------
extern "C" void kernel_launch(void* const* d_in, const int* in_sizes, int n_in,
                              void* d_out, int out_size)
{
    const float* x    = (const float*)d_in[0];
    const float* Wqkv = (const float*)d_in[1];
    const float* bqkv = (const float*)d_in[2];
    const float* Wm   = (const float*)d_in[3];
    const float* bm   = (const float*)d_in[4];
    const float* Wg   = (const float*)d_in[5];
    const float* bg   = (const float*)d_in[6];
    const float* Wr   = (const float*)d_in[7];
    const float* br   = (const float*)d_in[8];

    float* out  = (float*)d_out;
    float* attn = out + (size_t)B_ * C_ * N_;

    cudaFuncSetAttribute(mma_gemm, cudaFuncAttributeMaxDynamicSharedMemorySize, SMEM_TOTAL);

    __half *qkvRM, *vhT, *xhT, *yhT, *sq, *kh, *qh, *at, *yhR, *gph;
    __half *wqkvT, *wmT, *wgT, *wrT;
    cudaGetSymbolAddress((void**)&qkvRM, g_qkvRM);
    cudaGetSymbolAddress((void**)&vhT,  g_vhT);
    cudaGetSymbolAddress((void**)&xhT,  g_xhT);
    cudaGetSymbolAddress((void**)&yhT,  g_yhT);
    cudaGetSymbolAddress((void**)&sq,   g_sq);
    cudaGetSymbolAddress((void**)&kh,   g_kh);
    cudaGetSymbolAddress((void**)&qh,   g_qh);
    cudaGetSymbolAddress((void**)&at,   g_at);
    cudaGetSymbolAddress((void**)&yhR,  g_yhR);
    cudaGetSymbolAddress((void**)&gph,  g_gph);
    cudaGetSymbolAddress((void**)&wqkvT, g_wqkvT);
    cudaGetSymbolAddress((void**)&wmT,   g_wmT);
    cudaGetSymbolAddress((void**)&wgT,   g_wgT);
    cudaGetSymbolAddress((void**)&wrT,   g_wrT);

    // 0) retile weights + x
    retile_w<<<(3*C_*C_ + 255)/256, 256>>>(Wqkv, wqkvT, 3*C_, C_);
    retile_w<<<(2*C_*C_ + 255)/256, 256>>>(Wm,   wmT,   2*C_, C_);
    retile_w<<<(2*C_*C_ + 255)/256, 256>>>(Wg,   wgT,     C_, 2*C_);
    retile_w<<<(  C_*C_ + 255)/256, 256>>>(Wr,   wrT,     C_, C_);
    retile_x<<<(B_*C_*N_ + 255)/256, 256>>>(x, xhT);

    // 1) qkv (mode 3)
    mma_gemm<<<dim3(32, 12, B_), NTHREADS, SMEM_TOTAL>>>(
        wqkvT, 16, 0,
        xhT, 16, BMN_B, nullptr, 0, 0, 16,
        bqkv, 1.f, nullptr, qkvRM, vhT, nullptr, nullptr,
        16, 1, 3);

    // 2) mqk (mode 2)
    mma_gemm<<<dim3(32, 8, B_), NTHREADS, SMEM_TOTAL>>>(
        wmT, 16, 0,
        vhT, 16, BMN_B, nullptr, 0, 0, 16,
        bm, 1.f, nullptr, sq, kh, qkvRM, nullptr,
        16, 1, 2);

    // 3) softmax_q
    softmax_q<<<NROWS, 256>>>(sq, qh);

    // 4) scores (mode 0, NT)
    mma_gemm<<<dim3(4, 4, B_), NTHREADS, SMEM_TOTAL>>>(
        qh, 128, AFMT_BIG,
        kh, 128, AFMT_BIG, nullptr, 0, 0, 128,
        nullptr, 1.0f/sqrtf((float)C_), attn, nullptr, nullptr, nullptr, nullptr,
        128, 0, 0);

    // 5) softmax_attn
    softmax_attn<<<NROWS, 128>>>(attn, at);

    // 6) y (mode 4)
    mma_gemm<<<dim3(32, 4, B_), NTHREADS, SMEM_TOTAL>>>(
        at, 16, AFMT_AT,
        vhT, 16, BMN_B, nullptr, 0, 0, 16,
        nullptr, 1.f, nullptr, yhT, yhR, nullptr, nullptr,
        16, 1, 4);

    // 7) gate (mode 5)
    mma_gemm<<<dim3(32, 4, B_), NTHREADS, SMEM_TOTAL>>>(
        wgT, 32, 0,
        yhT, 16, BMN_B, xhT, 16, BMN_B, 16,
        bg, 1.f, nullptr, gph, nullptr, nullptr, nullptr,
        32, 1, 5);

    // 8) r + final fuse (mode 1)
    mma_gemm<<<dim3(32, 4, B_), NTHREADS, SMEM_TOTAL>>>(
        wrT, 16, 0,
        xhT, 16, BMN_B, nullptr, 0, 0, 16,
        br, 1.f, out, nullptr, nullptr, gph, yhR,
        16, 1, 1);
}

// round 15
// speedup vs baseline: 1.0340x; 1.0340x over previous
#include <cuda_runtime.h>
#include <cuda_fp16.h>
#include <math.h>
#include <stdint.h>
#include <stddef.h>

#define B_ 16
#define C_ 512
#define N_ 4096
#define NROWS (B_*C_)

#define TM 128
#define TN 128
#define TKC 32
#define NTHREADS 128

#define A_PAD 40
#define B_PAD_T 136
#define TILEA_H 5120
#define TILEB_H 4352
#define TILEA_BYTES 10240
#define TILEB_BYTES 8704

#define AH_BYTES 10240
#define STG_BYTES 20480
#define NSTAGE 5
#define SMEM_TILES 1024
#define SMEM_TOTAL (SMEM_TILES + NSTAGE*STG_BYTES)   // 103424, 2 CTAs/SM

// batch strides (halves)
#define QKVRM_B  ((size_t)1024*4096)
#define BMN_B    ((size_t)32*16*TILEB_H)
#define AFMT_BIG ((size_t)4*128*TILEA_H)
#define AFMT_AT  ((size_t)4*16*TILEA_H)
#define RM_B     ((size_t)C_*N_)

// ---------------- scratch ----------------
__device__ __half g_qkvRM[(size_t)B_*QKVRM_B];
__device__ __half g_vhT [(size_t)B_*BMN_B];
__device__ __half g_xhT [(size_t)B_*BMN_B];
__device__ __half g_yhT [(size_t)B_*BMN_B];
__device__ __half g_sq  [(size_t)B_*AFMT_BIG];
__device__ __half g_kh  [(size_t)B_*AFMT_BIG];
__device__ __half g_qh  [(size_t)B_*AFMT_BIG];
__device__ __half g_at  [(size_t)B_*AFMT_AT];
__device__ __half g_gph [(size_t)B_*RM_B];
__device__ __half g_wqkvT[12*16*TILEA_H];
__device__ __half g_wmT  [ 8*16*TILEA_H];
__device__ __half g_wgT  [ 4*32*TILEA_H];
__device__ __half g_wrT  [ 4*16*TILEA_H];

// ---------------- PTX helpers ----------------
__device__ __forceinline__ uint32_t smem_u32(const void* p){
    uint32_t a;
    asm("{ .reg .u64 t; cvta.to.shared.u64 t, %1; cvt.u32.u64 %0, t; }"
        : "=r"(a) : "l"(p));
    return a;
}
__device__ __forceinline__ void bulk_g2s(uint32_t dst, const void* src,
                                         uint32_t bytes, uint32_t bar){
    asm volatile(
        "cp.async.bulk.shared::cta.global.mbarrier::complete_tx::bytes "
        "[%0], [%1], %2, [%3];"
        :: "r"(dst), "l"(src), "r"(bytes), "r"(bar) : "memory");
}
__device__ __forceinline__ void mbar_init(uint32_t a, uint32_t n){
    asm volatile("mbarrier.init.shared.b64 [%0], %1;" :: "r"(a), "r"(n) : "memory");
}
__device__ __forceinline__ void mbar_expect(uint32_t a, uint32_t bytes){
    asm volatile("mbarrier.arrive.expect_tx.shared.b64 _, [%0], %1;"
                 :: "r"(a), "r"(bytes) : "memory");
}
__device__ __forceinline__ void mbar_wait(uint32_t a, uint32_t parity){
    asm volatile(
        "{\n\t.reg .pred P;\n\tWAITL%=:\n\t"
        "mbarrier.try_wait.parity.shared.b64 P, [%0], %1;\n\t"
        "@!P bra WAITL%=;\n\t}"
        :: "r"(a), "r"(parity) : "memory");
}
__device__ __forceinline__ void ldsm4(uint32_t* r, uint32_t addr){
    asm volatile("ldmatrix.sync.aligned.m8n8.x4.shared.b16 {%0,%1,%2,%3}, [%4];"
        : "=r"(r[0]), "=r"(r[1]), "=r"(r[2]), "=r"(r[3]) : "r"(addr));
}
__device__ __forceinline__ void ldsm4t(uint32_t* r, uint32_t addr){
    asm volatile("ldmatrix.sync.aligned.m8n8.x4.trans.shared.b16 {%0,%1,%2,%3}, [%4];"
        : "=r"(r[0]), "=r"(r[1]), "=r"(r[2]), "=r"(r[3]) : "r"(addr));
}
__device__ __forceinline__ void mma16816(float* c, const uint32_t* a, const uint32_t* b){
    asm volatile(
        "mma.sync.aligned.m16n8k16.row.col.f32.f16.f16.f32 "
        "{%0,%1,%2,%3}, {%4,%5,%6,%7}, {%8,%9}, {%0,%1,%2,%3};"
        : "+f"(c[0]), "+f"(c[1]), "+f"(c[2]), "+f"(c[3])
        : "r"(a[0]), "r"(a[1]), "r"(a[2]), "r"(a[3]), "r"(b[0]), "r"(b[1]));
}
__device__ __forceinline__ uint32_t pack_h2(float x, float y){
    __half2 p(__float2half_rn(x), __float2half_rn(y));
    return *(uint32_t*)&p;
}
__device__ __forceinline__ float2 unpack_h2(uint32_t u){
    __half2 p = *(__half2*)&u;
    return make_float2(__half2float(p.x), __half2float(p.y));
}

// ---------------------------------------------------------------------------
// fp16 GEMM, bulk-copy pipeline (5 stages). CTA 128x128, 4 warps, warp 64x64.
// modes: 0 scores / 1 final / 2 mqk / 3 qkv / 4 y / 5 gate
// mode 1: E1 = gph row-major, E2 = yhT MN-tiled.
// ---------------------------------------------------------------------------
__global__ void __launch_bounds__(NTHREADS, 2) mma_gemm(
    const __half* __restrict__ A, int aNC, size_t aTB,
    const __half* __restrict__ B1, int b1NC, size_t b1TB,
    const __half* __restrict__ B2, int b2NC, size_t b2TB, int K1c,
    const float* __restrict__ bias, float scale,
    float* __restrict__ Y32,
    __half* __restrict__ O1, __half* __restrict__ O2,
    const __half* __restrict__ E1, const __half* __restrict__ E2,
    int NC, int transB, int mode)
{
    extern __shared__ char smem[];
    const uint32_t sbase = smem_u32(smem);
    const uint32_t tiles = sbase + SMEM_TILES;

    const int tid  = threadIdx.x;
    const int lane = tid & 31;
    const int wid  = tid >> 5;
    const int wm   = wid & 1;
    const int wn   = wid >> 1;
    const int b    = blockIdx.z;
    const int m0   = blockIdx.y * TM;
    const int n0   = blockIdx.x * TN;

    const __half* Ab  = A  + (size_t)b * aTB;
    const __half* B1b = B1 + (size_t)b * b1TB;
    const __half* B2b = B2 ? (B2 + (size_t)b * b2TB) : (const __half*)0;

    const uint32_t expect = TILEA_BYTES + (transB ? TILEB_BYTES : TILEA_BYTES);

    if (tid == 0){
        #pragma unroll
        for (int s = 0; s < NSTAGE; s++) mbar_init(sbase + s*8, 1);
    }

    auto issue = [&](int kc){
        const int s = kc % NSTAGE;
        const uint32_t bar = sbase + s*8;
        mbar_expect(bar, expect);
        const __half* srcA = Ab + ((size_t)(m0 >> 7) * aNC + kc) * TILEA_H;
        bulk_g2s(tiles + s*STG_BYTES, srcA, TILEA_BYTES, bar);
        if (transB){
            const __half* srcB = (kc < K1c)
                ? B1b + ((size_t)(n0 >> 7) * b1NC + kc) * TILEB_H
                : B2b + ((size_t)(n0 >> 7) * b2NC + (kc - K1c)) * TILEB_H;
            bulk_g2s(tiles + s*STG_BYTES + AH_BYTES, srcB, TILEB_BYTES, bar);
        } else {
            const __half* srcB = B1b + ((size_t)(n0 >> 7) * b1NC + kc) * TILEA_H;
            bulk_g2s(tiles + s*STG_BYTES + AH_BYTES, srcB, TILEA_BYTES, bar);
        }
    };

    if (tid == 0){
        issue(0);
        if (NC > 1) issue(1);
        if (NC > 2) issue(2);
        if (NC > 3) issue(3);
    }
    __syncthreads();

    float acc[4][8][4];
    #pragma unroll
    for (int i = 0; i < 4; i++)
        #pragma unroll
        for (int j = 0; j < 8; j++)
            #pragma unroll
            for (int r = 0; r < 4; r++) acc[i][j][r] = 0.f;

    const int a_lrow = lane & 15;
    const int a_lcol = (lane >> 4) << 3;
    const int i4 = lane >> 3;
    const int r8 = lane & 7;
    const int kt = lane & 15;
    const int nh = lane >> 4;

    int st = 0, pa = 0;
    for (int kc = 0; kc < NC; kc++){
        mbar_wait(sbase + st*8, pa);
        __syncthreads();

        const uint32_t sa = tiles + st * STG_BYTES;
        const uint32_t sb = sa + AH_BYTES;

        uint32_t ah[2][4][4], bb[2][8][2];
        #pragma unroll
        for (int ks = 0; ks < 2; ks++){
            #pragma unroll
            for (int mt = 0; mt < 4; mt++){
                uint32_t ad = sa + 2 * ((wm*64 + mt*16 + a_lrow) * A_PAD + ks*16 + a_lcol);
                ldsm4(ah[ks][mt], ad);
            }
            #pragma unroll
            for (int p = 0; p < 4; p++){
                uint32_t r4[4];
                if (transB){
                    uint32_t bd = sb + 2 * ((ks*16 + kt) * B_PAD_T + wn*64 + (2*p + nh)*8);
                    ldsm4t(r4, bd);
                } else {
                    int row = wn*64 + (2*p + (i4 >> 1))*8 + r8;
                    int col = ks*16 + (i4 & 1)*8;
                    ldsm4(r4, sb + 2 * (row * A_PAD + col));
                }
                bb[ks][2*p][0]   = r4[0];
                bb[ks][2*p][1]   = r4[1];
                bb[ks][2*p+1][0] = r4[2];
                bb[ks][2*p+1][1] = r4[3];
            }
        }

        if (tid == 0 && kc + 4 < NC) issue(kc + 4);

        #pragma unroll
        for (int ks = 0; ks < 2; ks++)
            #pragma unroll
            for (int mt = 0; mt < 4; mt++)
                #pragma unroll
                for (int nt = 0; nt < 8; nt++)
                    mma16816(acc[mt][nt], ah[ks][mt], bb[ks][nt]);

        if (++st == NSTAGE){ st = 0; pa ^= 1; }
    }

    // ---- epilogue ----
    const int g = lane >> 2;
    const int t = lane & 3;
    #pragma unroll
    for (int mt = 0; mt < 4; mt++){
        int m = m0 + wm*64 + mt*16 + g;
        float bi_lo = bias ? bias[m]     : 0.f;
        float bi_hi = bias ? bias[m + 8] : 0.f;
        #pragma unroll
        for (int nt = 0; nt < 8; nt++){
            int nn = n0 + wn*64 + nt*8 + 2*t;
            float v00 = acc[mt][nt][0] * scale + bi_lo;
            float v01 = acc[mt][nt][1] * scale + bi_lo;
            float v10 = acc[mt][nt][2] * scale + bi_hi;
            float v11 = acc[mt][nt][3] * scale + bi_hi;

            if (mode == 0){
                size_t off0 = (size_t)b*((size_t)C_*C_) + (size_t)m*C_ + nn;
                size_t off1 = off0 + (size_t)8*C_;
                float2 o0 = {v00, v01}, o1 = {v10, v11};
                *(float2*)(Y32 + off0) = o0;
                *(float2*)(Y32 + off1) = o1;
            } else if (mode == 3){
                if (m < 1024){
                    size_t o0 = (size_t)b*QKVRM_B + (size_t)m*N_ + nn;
                    *(uint32_t*)(O1 + o0)                = pack_h2(v00, v01);
                    *(uint32_t*)(O1 + o0 + 8*(size_t)N_) = pack_h2(v10, v11);
                } else {
                    int c = m - 1024;
                    size_t base = (size_t)b*BMN_B
                        + ((size_t)(nn>>7)*16 + (c>>5))*TILEB_H + (nn & 127);
                    *(uint32_t*)(O2 + base + (size_t)(c & 31)*B_PAD_T)       = pack_h2(v00, v01);
                    *(uint32_t*)(O2 + base + (size_t)((c & 31) + 8)*B_PAD_T) = pack_h2(v10, v11);
                }
            } else if (mode == 2){
                size_t eo = (size_t)b*QKVRM_B + (size_t)m*N_ + nn;
                float2 q0 = unpack_h2(*(const uint32_t*)(E1 + eo));
                float2 q1 = unpack_h2(*(const uint32_t*)(E1 + eo + 8*(size_t)N_));
                float p00 = v00*q0.x, p01 = v01*q0.y, p10 = v10*q1.x, p11 = v11*q1.y;
                bool neg = (m < 512);
                p00 = neg ? -fmaxf(p00,0.f) : fmaxf(p00,0.f);
                p01 = neg ? -fmaxf(p01,0.f) : fmaxf(p01,0.f);
                p10 = neg ? -fmaxf(p10,0.f) : fmaxf(p10,0.f);
                p11 = neg ? -fmaxf(p11,0.f) : fmaxf(p11,0.f);
                __half* dst = neg ? O1 : O2;
                int mm = neg ? m : (m - 512);
                size_t base = (size_t)b*AFMT_BIG
                    + ((size_t)(mm>>7)*128 + (nn>>5))*TILEA_H + (nn & 31);
                *(uint32_t*)(dst + base + (size_t)(mm & 127)*A_PAD)       = pack_h2(p00, p01);
                *(uint32_t*)(dst + base + (size_t)((mm & 127) + 8)*A_PAD) = pack_h2(p10, p11);
            } else if (mode == 4){
                size_t bt = (size_t)b*BMN_B
                    + ((size_t)(nn>>7)*16 + (m>>5))*TILEB_H + (nn & 127);
                *(uint32_t*)(O1 + bt + (size_t)(m & 31)*B_PAD_T)       = pack_h2(v00, v01);
                *(uint32_t*)(O1 + bt + (size_t)((m & 31) + 8)*B_PAD_T) = pack_h2(v10, v11);
            } else if (mode == 5){
                size_t o0 = (size_t)b*RM_B + (size_t)m*N_ + nn;
                *(uint32_t*)(O1 + o0)                = pack_h2(v00, v01);
                *(uint32_t*)(O1 + o0 + 8*(size_t)N_) = pack_h2(v10, v11);
            } else { // mode 1: gp row-major, y MN-tiled
                size_t eo0 = (size_t)b*RM_B + (size_t)m*N_ + nn;
                size_t eo1 = eo0 + 8*(size_t)N_;
                float2 gp0 = unpack_h2(*(const uint32_t*)(E1 + eo0));
                float2 gp1 = unpack_h2(*(const uint32_t*)(E1 + eo1));
                size_t yt = (size_t)b*BMN_B
                    + ((size_t)(nn>>7)*16 + (m>>5))*TILEB_H + (nn & 127);
                float2 y0 = unpack_h2(*(const uint32_t*)(E2 + yt + (size_t)(m & 31)*B_PAD_T));
                float2 y1 = unpack_h2(*(const uint32_t*)(E2 + yt + (size_t)((m & 31) + 8)*B_PAD_T));
                float s0 = 1.f/(1.f+__expf(-gp0.x));
                float s1 = 1.f/(1.f+__expf(-gp0.y));
                float s2 = 1.f/(1.f+__expf(-gp1.x));
                float s3 = 1.f/(1.f+__expf(-gp1.y));
                size_t off0 = (size_t)b*RM_B + (size_t)m*N_ + nn;
                size_t off1 = off0 + 8*(size_t)N_;
                float2 o0, o1;
                o0.x = y0.x + s0*(v00 - y0.x);
                o0.y = y0.y + s1*(v01 - y0.y);
                o1.x = y1.x + s2*(v10 - y1.x);
                o1.y = y1.y + s3*(v11 - y1.y);
                *(float2*)(Y32 + off0) = o0;
                *(float2*)(Y32 + off1) = o1;
            }
        }
    }
}

// ---------------------------------------------------------------------------
// Single fused retile: all 4 weights (A-fmt) + x (MN-fmt)
#define RW0 (3*C_*C_)
#define RW1 (2*C_*C_)
#define RW2 (2*C_*C_)
#define RW3 (C_*C_)
#define RX  (B_*C_*N_)
#define RT_TOTAL (RW0+RW1+RW2+RW3+RX)

__global__ void retile_all(
    const float* __restrict__ wq, __half* __restrict__ dq,
    const float* __restrict__ wm, __half* __restrict__ dm,
    const float* __restrict__ wg, __half* __restrict__ dg,
    const float* __restrict__ wr, __half* __restrict__ dr,
    const float* __restrict__ x,  __half* __restrict__ dx)
{
    int i = blockIdx.x * 256 + threadIdx.x;
    if (i >= RT_TOTAL) return;
    if (i < RW0+RW1+RW2+RW3){
        const float* s; __half* d; int off, K;
        if (i < RW0){ s = wq; d = dq; off = i; K = C_; }
        else if (i < RW0+RW1){ s = wm; d = dm; off = i - RW0; K = C_; }
        else if (i < RW0+RW1+RW2){ s = wg; d = dg; off = i - RW0 - RW1; K = 2*C_; }
        else { s = wr; d = dr; off = i - RW0 - RW1 - RW2; K = C_; }
        int m = off / K, k = off % K;
        size_t o = ((size_t)(m>>7)*(K>>5) + (k>>5))*TILEA_H
                 + (size_t)(m & 127)*A_PAD + (k & 31);
        d[o] = __float2half_rn(s[off]);
    } else {
        int j = i - (RW0+RW1+RW2+RW3);
        int b = j / (C_*N_);
        int rem = j - b*(C_*N_);
        int c = rem >> 12, pos = rem & 4095;
        size_t o = (size_t)b*BMN_B + ((size_t)(pos>>7)*16 + (c>>5))*TILEB_H
                 + (size_t)(c & 31)*B_PAD_T + (pos & 127);
        dx[o] = __float2half_rn(x[j]);
    }
}

// ---------------------------------------------------------------------------
__global__ void softmax_q(const __half* __restrict__ sq, __half* __restrict__ qh)
{
    __shared__ float red[8];
    __shared__ float bc;
    const int row = blockIdx.x;
    const int b = row >> 9, c = row & 511;
    const size_t tb = (size_t)b*AFMT_BIG + (size_t)(c>>7)*128*TILEA_H
                    + (size_t)(c & 127)*A_PAD;

    float v[16];
    float mx = -1e30f;
    #pragma unroll
    for (int i = 0; i < 8; i++){
        int hidx = threadIdx.x + (i << 8);
        int n = hidx << 1;
        size_t off = tb + (size_t)(n>>5)*TILEA_H + (n & 31);
        float2 f = unpack_h2(*(const uint32_t*)(sq + off));
        v[2*i] = f.x; v[2*i+1] = f.y;
        mx = fmaxf(mx, fmaxf(f.x, f.y));
    }
    #pragma unroll
    for (int off = 16; off; off >>= 1)
        mx = fmaxf(mx, __shfl_xor_sync(0xffffffffu, mx, off));
    if ((threadIdx.x & 31) == 0) red[threadIdx.x >> 5] = mx;
    __syncthreads();
    if (threadIdx.x == 0){
        float tv = red[0];
        #pragma unroll
        for (int i = 1; i < 8; i++) tv = fmaxf(tv, red[i]);
        bc = tv;
    }
    __syncthreads();
    mx = bc;

    float sm = 0.f;
    #pragma unroll
    for (int i = 0; i < 16; i++){
        v[i] = __expf(v[i] - mx);
        sm += v[i];
    }
    #pragma unroll
    for (int off = 16; off; off >>= 1)
        sm += __shfl_xor_sync(0xffffffffu, sm, off);
    __syncthreads();
    if ((threadIdx.x & 31) == 0) red[threadIdx.x >> 5] = sm;
    __syncthreads();
    if (threadIdx.x == 0){
        float tv = 0.f;
        #pragma unroll
        for (int i = 0; i < 8; i++) tv += red[i];
        bc = tv;
    }
    __syncthreads();
    const float rinv = 1.f / bc;
    #pragma unroll
    for (int i = 0; i < 8; i++){
        int hidx = threadIdx.x + (i << 8);
        int n = hidx << 1;
        size_t off = tb + (size_t)(n>>5)*TILEA_H + (n & 31);
        *(uint32_t*)(qh + off) = pack_h2(v[2*i]*rinv, v[2*i+1]*rinv);
    }
}

// ---------------------------------------------------------------------------
__global__ void softmax_attn(float* __restrict__ S, __half* __restrict__ at)
{
    __shared__ float red[4];
    __shared__ float bc;
    const int row = blockIdx.x;
    const int b = row >> 9, c = row & 511;
    float* p = S + (size_t)row * 512;
    const size_t tb = (size_t)b*AFMT_AT + (size_t)(c>>7)*16*TILEA_H
                    + (size_t)(c & 127)*A_PAD;

    float v[4];
    float mx = -1e30f;
    #pragma unroll
    for (int i = 0; i < 4; i++){
        int idx = threadIdx.x + (i << 7);
        v[i] = p[idx];
        mx = fmaxf(mx, v[i]);
    }
    #pragma unroll
    for (int off = 16; off; off >>= 1)
        mx = fmaxf(mx, __shfl_xor_sync(0xffffffffu, mx, off));
    if ((threadIdx.x & 31) == 0) red[threadIdx.x >> 5] = mx;
    __syncthreads();
    if (threadIdx.x == 0)
        bc = fmaxf(fmaxf(red[0], red[1]), fmaxf(red[2], red[3]));
    __syncthreads();
    mx = bc;

    float sm = 0.f;
    #pragma unroll
    for (int i = 0; i < 4; i++){
        v[i] = __expf(v[i] - mx);
        sm += v[i];
    }
    #pragma unroll
    for (int off = 16; off; off >>= 1)
        sm += __shfl_xor_sync(0xffffffffu, sm, off);
    __syncthreads();
    if ((threadIdx.x & 31) == 0) red[threadIdx.x >> 5] = sm;
    __syncthreads();
    if (threadIdx.x == 0) bc = red[0] + red[1] + red[2] + red[3];
    __syncthreads();
    const float rinv = 1.f / bc;
    #pragma unroll
    for (int i = 0; i < 4; i++){
        int d = threadIdx.x + (i << 7);
        float f = v[i] * rinv;
        p[d] = f;
        at[tb + (size_t)(d>>5)*TILEA_H + (d & 31)] = __float2half_rn(f);
    }
}

// ---------------------------------------------------------------------------
extern "C" void kernel_launch(void* const* d_in, const int* in_sizes, int n_in,
                              void* d_out, int out_size)
{
    const float* x    = (const float*)d_in[0];
    const float* Wqkv = (const float*)d_in[1];
    const float* bqkv = (const float*)d_in[2];
    const float* Wm   = (const float*)d_in[3];
    const float* bm   = (const float*)d_in[4];
    const float* Wg   = (const float*)d_in[5];
    const float* bg   = (const float*)d_in[6];
    const float* Wr   = (const float*)d_in[7];
    const float* br   = (const float*)d_in[8];

    float* out  = (float*)d_out;
    float* attn = out + (size_t)B_ * C_ * N_;

    cudaFuncSetAttribute(mma_gemm, cudaFuncAttributeMaxDynamicSharedMemorySize, SMEM_TOTAL);

    __half *qkvRM, *vhT, *xhT, *yhT, *sq, *kh, *qh, *at, *gph;
    __half *wqkvT, *wmT, *wgT, *wrT;
    cudaGetSymbolAddress((void**)&qkvRM, g_qkvRM);
    cudaGetSymbolAddress((void**)&vhT,  g_vhT);
    cudaGetSymbolAddress((void**)&xhT,  g_xhT);
    cudaGetSymbolAddress((void**)&yhT,  g_yhT);
    cudaGetSymbolAddress((void**)&sq,   g_sq);
    cudaGetSymbolAddress((void**)&kh,   g_kh);
    cudaGetSymbolAddress((void**)&qh,   g_qh);
    cudaGetSymbolAddress((void**)&at,   g_at);
    cudaGetSymbolAddress((void**)&gph,  g_gph);
    cudaGetSymbolAddress((void**)&wqkvT, g_wqkvT);
    cudaGetSymbolAddress((void**)&wmT,   g_wmT);
    cudaGetSymbolAddress((void**)&wgT,   g_wgT);
    cudaGetSymbolAddress((void**)&wrT,   g_wrT);

    // 0) fused retile of all weights + x
    retile_all<<<(RT_TOTAL + 255)/256, 256>>>(
        Wqkv, wqkvT, Wm, wmT, Wg, wgT, Wr, wrT, x, xhT);

    // 1) qkv (mode 3)
    mma_gemm<<<dim3(32, 12, B_), NTHREADS, SMEM_TOTAL>>>(
        wqkvT, 16, 0,
        xhT, 16, BMN_B, nullptr, 0, 0, 16,
        bqkv, 1.f, nullptr, qkvRM, vhT, nullptr, nullptr,
        16, 1, 3);

    // 2) mqk (mode 2)
    mma_gemm<<<dim3(32, 8, B_), NTHREADS, SMEM_TOTAL>>>(
        wmT, 16, 0,
        vhT, 16, BMN_B, nullptr, 0, 0, 16,
        bm, 1.f, nullptr, sq, kh, qkvRM, nullptr,
        16, 1, 2);

    // 3) softmax_q
    softmax_q<<<NROWS, 256>>>(sq, qh);

    // 4) scores (mode 0, NT, K=4096)
    mma_gemm<<<dim3(4, 4, B_), NTHREADS, SMEM_TOTAL>>>(
        qh, 128, AFMT_BIG,
        kh, 128, AFMT_BIG, nullptr, 0, 0, 128,
        nullptr, 1.0f/sqrtf((float)C_), attn, nullptr, nullptr, nullptr, nullptr,
        128, 0, 0);

    // 5) softmax_attn
    softmax_attn<<<NROWS, 128>>>(attn, at);

    // 6) y (mode 4) -> yhT tiles only
    mma_gemm<<<dim3(32, 4, B_), NTHREADS, SMEM_TOTAL>>>(
        at, 16, AFMT_AT,
        vhT, 16, BMN_B, nullptr, 0, 0, 16,
        nullptr, 1.f, nullptr, yhT, nullptr, nullptr, nullptr,
        16, 1, 4);

    // 7) gate (mode 5)
    mma_gemm<<<dim3(32, 4, B_), NTHREADS, SMEM_TOTAL>>>(
        wgT, 32, 0,
        yhT, 16, BMN_B, xhT, 16, BMN_B, 16,
        bg, 1.f, nullptr, gph, nullptr, nullptr, nullptr,
        32, 1, 5);

    // 8) r + final fuse (mode 1; y read from tiles)
    mma_gemm<<<dim3(32, 4, B_), NTHREADS, SMEM_TOTAL>>>(
        wrT, 16, 0,
        xhT, 16, BMN_B, nullptr, 0, 0, 16,
        br, 1.f, out, nullptr, nullptr, gph, yhT,
        16, 1, 1);
}

// round 16
// speedup vs baseline: 1.0348x; 1.0007x over previous
#include <cuda_runtime.h>
#include <cuda_fp16.h>
#include <math.h>
#include <stdint.h>
#include <stddef.h>

#define B_ 16
#define C_ 512
#define N_ 4096
#define NROWS (B_*C_)

#define TM 128
#define TN 128
#define TKC 32
#define NTHREADS 128

#define A_PAD 40
#define B_PAD_T 136
#define TILEA_H 5120
#define TILEB_H 4352
#define TILEA_BYTES 10240
#define TILEB_BYTES 8704

#define AH_BYTES 10240
#define STG_BYTES 20480
#define NSTAGE 5
#define SMEM_TILES 1024
#define SMEM_TOTAL (SMEM_TILES + NSTAGE*STG_BYTES)   // 103424, 2 CTAs/SM

// batch strides (halves)
#define QKVRM_B  ((size_t)1024*4096)
#define BMN_B    ((size_t)32*16*TILEB_H)
#define AFMT_BIG ((size_t)4*128*TILEA_H)
#define AFMT_AT  ((size_t)4*16*TILEA_H)
#define RM_B     ((size_t)C_*N_)

// ---------------- scratch ----------------
__device__ __half g_qkvRM[(size_t)B_*QKVRM_B];
__device__ __half g_vhT [(size_t)B_*BMN_B];
__device__ __half g_xhT [(size_t)B_*BMN_B];
__device__ __half g_yhT [(size_t)B_*BMN_B];
__device__ __half g_sq  [(size_t)B_*AFMT_BIG];
__device__ __half g_kh  [(size_t)B_*AFMT_BIG];
__device__ __half g_qh  [(size_t)B_*AFMT_BIG];
__device__ __half g_at  [(size_t)B_*AFMT_AT];
__device__ __half g_gph [(size_t)B_*RM_B];
__device__ __half g_wqkvT[12*16*TILEA_H];
__device__ __half g_wmT  [ 8*16*TILEA_H];
__device__ __half g_wgT  [ 4*32*TILEA_H];
__device__ __half g_wrT  [ 4*16*TILEA_H];

// ---------------- PTX helpers ----------------
__device__ __forceinline__ uint32_t smem_u32(const void* p){
    uint32_t a;
    asm("{ .reg .u64 t; cvta.to.shared.u64 t, %1; cvt.u32.u64 %0, t; }"
        : "=r"(a) : "l"(p));
    return a;
}
__device__ __forceinline__ void bulk_g2s(uint32_t dst, const void* src,
                                         uint32_t bytes, uint32_t bar){
    asm volatile(
        "cp.async.bulk.shared::cta.global.mbarrier::complete_tx::bytes "
        "[%0], [%1], %2, [%3];"
        :: "r"(dst), "l"(src), "r"(bytes), "r"(bar) : "memory");
}
__device__ __forceinline__ void mbar_init(uint32_t a, uint32_t n){
    asm volatile("mbarrier.init.shared.b64 [%0], %1;" :: "r"(a), "r"(n) : "memory");
}
__device__ __forceinline__ void mbar_expect(uint32_t a, uint32_t bytes){
    asm volatile("mbarrier.arrive.expect_tx.shared.b64 _, [%0], %1;"
                 :: "r"(a), "r"(bytes) : "memory");
}
__device__ __forceinline__ void mbar_wait(uint32_t a, uint32_t parity){
    asm volatile(
        "{\n\t.reg .pred P;\n\tWAITL%=:\n\t"
        "mbarrier.try_wait.parity.shared.b64 P, [%0], %1;\n\t"
        "@!P bra WAITL%=;\n\t}"
        :: "r"(a), "r"(parity) : "memory");
}
__device__ __forceinline__ void ldsm4(uint32_t* r, uint32_t addr){
    asm volatile("ldmatrix.sync.aligned.m8n8.x4.shared.b16 {%0,%1,%2,%3}, [%4];"
        : "=r"(r[0]), "=r"(r[1]), "=r"(r[2]), "=r"(r[3]) : "r"(addr));
}
__device__ __forceinline__ void ldsm4t(uint32_t* r, uint32_t addr){
    asm volatile("ldmatrix.sync.aligned.m8n8.x4.trans.shared.b16 {%0,%1,%2,%3}, [%4];"
        : "=r"(r[0]), "=r"(r[1]), "=r"(r[2]), "=r"(r[3]) : "r"(addr));
}
__device__ __forceinline__ void mma16816(float* c, const uint32_t* a, const uint32_t* b){
    asm volatile(
        "mma.sync.aligned.m16n8k16.row.col.f32.f16.f16.f32 "
        "{%0,%1,%2,%3}, {%4,%5,%6,%7}, {%8,%9}, {%0,%1,%2,%3};"
        : "+f"(c[0]), "+f"(c[1]), "+f"(c[2]), "+f"(c[3])
        : "r"(a[0]), "r"(a[1]), "r"(a[2]), "r"(a[3]), "r"(b[0]), "r"(b[1]));
}
__device__ __forceinline__ uint32_t pack_h2(float x, float y){
    __half2 p(__float2half_rn(x), __float2half_rn(y));
    return *(uint32_t*)&p;
}
__device__ __forceinline__ float2 unpack_h2(uint32_t u){
    __half2 p = *(__half2*)&u;
    return make_float2(__half2float(p.x), __half2float(p.y));
}

// ---------------------------------------------------------------------------
// fp16 GEMM, bulk-copy pipeline (5 stages). CTA 128x128, 4 warps, warp 64x64.
// modes: 0 scores / 1 final / 2 mqk / 3 qkv / 4 y / 5 gate
// ---------------------------------------------------------------------------
__global__ void __launch_bounds__(NTHREADS, 2) mma_gemm(
    const __half* __restrict__ A, int aNC, size_t aTB,
    const __half* __restrict__ B1, int b1NC, size_t b1TB,
    const __half* __restrict__ B2, int b2NC, size_t b2TB, int K1c,
    const float* __restrict__ bias, float scale,
    float* __restrict__ Y32,
    __half* __restrict__ O1, __half* __restrict__ O2,
    const __half* __restrict__ E1, const __half* __restrict__ E2,
    int NC, int transB, int mode)
{
    extern __shared__ char smem[];
    const uint32_t sbase = smem_u32(smem);
    const uint32_t tiles = sbase + SMEM_TILES;

    const int tid  = threadIdx.x;
    const int lane = tid & 31;
    const int wid  = tid >> 5;
    const int wm   = wid & 1;
    const int wn   = wid >> 1;
    const int b    = blockIdx.z;
    const int m0   = blockIdx.y * TM;
    const int n0   = blockIdx.x * TN;

    const __half* Ab  = A  + (size_t)b * aTB;
    const __half* B1b = B1 + (size_t)b * b1TB;
    const __half* B2b = B2 ? (B2 + (size_t)b * b2TB) : (const __half*)0;

    const uint32_t expect = TILEA_BYTES + (transB ? TILEB_BYTES : TILEA_BYTES);

    if (tid == 0){
        #pragma unroll
        for (int s = 0; s < NSTAGE; s++) mbar_init(sbase + s*8, 1);
    }

    auto issue = [&](int kc){
        const int s = kc % NSTAGE;
        const uint32_t bar = sbase + s*8;
        mbar_expect(bar, expect);
        const __half* srcA = Ab + ((size_t)(m0 >> 7) * aNC + kc) * TILEA_H;
        bulk_g2s(tiles + s*STG_BYTES, srcA, TILEA_BYTES, bar);
        if (transB){
            const __half* srcB = (kc < K1c)
                ? B1b + ((size_t)(n0 >> 7) * b1NC + kc) * TILEB_H
                : B2b + ((size_t)(n0 >> 7) * b2NC + (kc - K1c)) * TILEB_H;
            bulk_g2s(tiles + s*STG_BYTES + AH_BYTES, srcB, TILEB_BYTES, bar);
        } else {
            const __half* srcB = B1b + ((size_t)(n0 >> 7) * b1NC + kc) * TILEA_H;
            bulk_g2s(tiles + s*STG_BYTES + AH_BYTES, srcB, TILEA_BYTES, bar);
        }
    };

    if (tid == 0){
        issue(0);
        if (NC > 1) issue(1);
        if (NC > 2) issue(2);
        if (NC > 3) issue(3);
    }
    __syncthreads();

    float acc[4][8][4];
    #pragma unroll
    for (int i = 0; i < 4; i++)
        #pragma unroll
        for (int j = 0; j < 8; j++)
            #pragma unroll
            for (int r = 0; r < 4; r++) acc[i][j][r] = 0.f;

    const int a_lrow = lane & 15;
    const int a_lcol = (lane >> 4) << 3;
    const int i4 = lane >> 3;
    const int r8 = lane & 7;
    const int kt = lane & 15;
    const int nh = lane >> 4;

    int st = 0, pa = 0;
    for (int kc = 0; kc < NC; kc++){
        mbar_wait(sbase + st*8, pa);
        __syncthreads();

        const uint32_t sa = tiles + st * STG_BYTES;
        const uint32_t sb = sa + AH_BYTES;

        uint32_t ah[2][4][4], bb[2][8][2];
        #pragma unroll
        for (int ks = 0; ks < 2; ks++){
            #pragma unroll
            for (int mt = 0; mt < 4; mt++){
                uint32_t ad = sa + 2 * ((wm*64 + mt*16 + a_lrow) * A_PAD + ks*16 + a_lcol);
                ldsm4(ah[ks][mt], ad);
            }
            #pragma unroll
            for (int p = 0; p < 4; p++){
                uint32_t r4[4];
                if (transB){
                    uint32_t bd = sb + 2 * ((ks*16 + kt) * B_PAD_T + wn*64 + (2*p + nh)*8);
                    ldsm4t(r4, bd);
                } else {
                    int row = wn*64 + (2*p + (i4 >> 1))*8 + r8;
                    int col = ks*16 + (i4 & 1)*8;
                    ldsm4(r4, sb + 2 * (row * A_PAD + col));
                }
                bb[ks][2*p][0]   = r4[0];
                bb[ks][2*p][1]   = r4[1];
                bb[ks][2*p+1][0] = r4[2];
                bb[ks][2*p+1][1] = r4[3];
            }
        }

        if (tid == 0 && kc + 4 < NC) issue(kc + 4);

        #pragma unroll
        for (int ks = 0; ks < 2; ks++)
            #pragma unroll
            for (int mt = 0; mt < 4; mt++)
                #pragma unroll
                for (int nt = 0; nt < 8; nt++)
                    mma16816(acc[mt][nt], ah[ks][mt], bb[ks][nt]);

        if (++st == NSTAGE){ st = 0; pa ^= 1; }
    }

    // ---- epilogue ----
    const int g = lane >> 2;
    const int t = lane & 3;
    #pragma unroll
    for (int mt = 0; mt < 4; mt++){
        int m = m0 + wm*64 + mt*16 + g;
        float bi_lo = bias ? bias[m]     : 0.f;
        float bi_hi = bias ? bias[m + 8] : 0.f;
        #pragma unroll
        for (int nt = 0; nt < 8; nt++){
            int nn = n0 + wn*64 + nt*8 + 2*t;
            float v00 = acc[mt][nt][0] * scale + bi_lo;
            float v01 = acc[mt][nt][1] * scale + bi_lo;
            float v10 = acc[mt][nt][2] * scale + bi_hi;
            float v11 = acc[mt][nt][3] * scale + bi_hi;

            if (mode == 0){
                size_t off0 = (size_t)b*((size_t)C_*C_) + (size_t)m*C_ + nn;
                size_t off1 = off0 + (size_t)8*C_;
                float2 o0 = {v00, v01}, o1 = {v10, v11};
                *(float2*)(Y32 + off0) = o0;
                *(float2*)(Y32 + off1) = o1;
            } else if (mode == 3){
                if (m < 1024){
                    size_t o0 = (size_t)b*QKVRM_B + (size_t)m*N_ + nn;
                    *(uint32_t*)(O1 + o0)                = pack_h2(v00, v01);
                    *(uint32_t*)(O1 + o0 + 8*(size_t)N_) = pack_h2(v10, v11);
                } else {
                    int c = m - 1024;
                    size_t base = (size_t)b*BMN_B
                        + ((size_t)(nn>>7)*16 + (c>>5))*TILEB_H + (nn & 127);
                    *(uint32_t*)(O2 + base + (size_t)(c & 31)*B_PAD_T)       = pack_h2(v00, v01);
                    *(uint32_t*)(O2 + base + (size_t)((c & 31) + 8)*B_PAD_T) = pack_h2(v10, v11);
                }
            } else if (mode == 2){
                size_t eo = (size_t)b*QKVRM_B + (size_t)m*N_ + nn;
                float2 q0 = unpack_h2(*(const uint32_t*)(E1 + eo));
                float2 q1 = unpack_h2(*(const uint32_t*)(E1 + eo + 8*(size_t)N_));
                float p00 = v00*q0.x, p01 = v01*q0.y, p10 = v10*q1.x, p11 = v11*q1.y;
                bool neg = (m < 512);
                p00 = neg ? -fmaxf(p00,0.f) : fmaxf(p00,0.f);
                p01 = neg ? -fmaxf(p01,0.f) : fmaxf(p01,0.f);
                p10 = neg ? -fmaxf(p10,0.f) : fmaxf(p10,0.f);
                p11 = neg ? -fmaxf(p11,0.f) : fmaxf(p11,0.f);
                __half* dst = neg ? O1 : O2;
                int mm = neg ? m : (m - 512);
                size_t base = (size_t)b*AFMT_BIG
                    + ((size_t)(mm>>7)*128 + (nn>>5))*TILEA_H + (nn & 31);
                *(uint32_t*)(dst + base + (size_t)(mm & 127)*A_PAD)       = pack_h2(p00, p01);
                *(uint32_t*)(dst + base + (size_t)((mm & 127) + 8)*A_PAD) = pack_h2(p10, p11);
            } else if (mode == 4){
                size_t bt = (size_t)b*BMN_B
                    + ((size_t)(nn>>7)*16 + (m>>5))*TILEB_H + (nn & 127);
                *(uint32_t*)(O1 + bt + (size_t)(m & 31)*B_PAD_T)       = pack_h2(v00, v01);
                *(uint32_t*)(O1 + bt + (size_t)((m & 31) + 8)*B_PAD_T) = pack_h2(v10, v11);
            } else if (mode == 5){
                size_t o0 = (size_t)b*RM_B + (size_t)m*N_ + nn;
                *(uint32_t*)(O1 + o0)                = pack_h2(v00, v01);
                *(uint32_t*)(O1 + o0 + 8*(size_t)N_) = pack_h2(v10, v11);
            } else { // mode 1
                size_t eo0 = (size_t)b*RM_B + (size_t)m*N_ + nn;
                size_t eo1 = eo0 + 8*(size_t)N_;
                float2 gp0 = unpack_h2(*(const uint32_t*)(E1 + eo0));
                float2 gp1 = unpack_h2(*(const uint32_t*)(E1 + eo1));
                size_t yt = (size_t)b*BMN_B
                    + ((size_t)(nn>>7)*16 + (m>>5))*TILEB_H + (nn & 127);
                float2 y0 = unpack_h2(*(const uint32_t*)(E2 + yt + (size_t)(m & 31)*B_PAD_T));
                float2 y1 = unpack_h2(*(const uint32_t*)(E2 + yt + (size_t)((m & 31) + 8)*B_PAD_T));
                float s0 = 1.f/(1.f+__expf(-gp0.x));
                float s1 = 1.f/(1.f+__expf(-gp0.y));
                float s2 = 1.f/(1.f+__expf(-gp1.x));
                float s3 = 1.f/(1.f+__expf(-gp1.y));
                size_t off0 = (size_t)b*RM_B + (size_t)m*N_ + nn;
                size_t off1 = off0 + 8*(size_t)N_;
                float2 o0, o1;
                o0.x = y0.x + s0*(v00 - y0.x);
                o0.y = y0.y + s1*(v01 - y0.y);
                o1.x = y1.x + s2*(v10 - y1.x);
                o1.y = y1.y + s3*(v11 - y1.y);
                *(float2*)(Y32 + off0) = o0;
                *(float2*)(Y32 + off1) = o1;
            }
        }
    }
}

// ---------------------------------------------------------------------------
#define RW0 (3*C_*C_)
#define RW1 (2*C_*C_)
#define RW2 (2*C_*C_)
#define RW3 (C_*C_)
#define RX  (B_*C_*N_)
#define RT_TOTAL (RW0+RW1+RW2+RW3+RX)

__global__ void retile_all(
    const float* __restrict__ wq, __half* __restrict__ dq,
    const float* __restrict__ wm, __half* __restrict__ dm,
    const float* __restrict__ wg, __half* __restrict__ dg,
    const float* __restrict__ wr, __half* __restrict__ dr,
    const float* __restrict__ x,  __half* __restrict__ dx)
{
    int i = blockIdx.x * 256 + threadIdx.x;
    if (i >= RT_TOTAL) return;
    if (i < RW0+RW1+RW2+RW3){
        const float* s; __half* d; int off, K;
        if (i < RW0){ s = wq; d = dq; off = i; K = C_; }
        else if (i < RW0+RW1){ s = wm; d = dm; off = i - RW0; K = C_; }
        else if (i < RW0+RW1+RW2){ s = wg; d = dg; off = i - RW0 - RW1; K = 2*C_; }
        else { s = wr; d = dr; off = i - RW0 - RW1 - RW2; K = C_; }
        int m = off / K, k = off % K;
        size_t o = ((size_t)(m>>7)*(K>>5) + (k>>5))*TILEA_H
                 + (size_t)(m & 127)*A_PAD + (k & 31);
        d[o] = __float2half_rn(s[off]);
    } else {
        int j = i - (RW0+RW1+RW2+RW3);
        int b = j / (C_*N_);
        int rem = j - b*(C_*N_);
        int c = rem >> 12, pos = rem & 4095;
        size_t o = (size_t)b*BMN_B + ((size_t)(pos>>7)*16 + (c>>5))*TILEB_H
                 + (size_t)(c & 31)*B_PAD_T + (pos & 127);
        dx[o] = __float2half_rn(x[j]);
    }
}

// ---------------------------------------------------------------------------
// softmax over sq tiles -> qh tiles, fully uint4-coalesced I/O.
// Row = 128 segments of 32 halves (64 B) at stride TILEA_H; 512 uint4/row.
__global__ void softmax_q(const __half* __restrict__ sq, __half* __restrict__ qh)
{
    __shared__ float red[8];
    __shared__ float bc;
    const int row = blockIdx.x;
    const int b = row >> 9, c = row & 511;
    const size_t tb = (size_t)b*AFMT_BIG + (size_t)(c>>7)*128*TILEA_H
                    + (size_t)(c & 127)*A_PAD;

    float v[16];
    float mx = -1e30f;
    #pragma unroll
    for (int i = 0; i < 2; i++){
        int u = threadIdx.x + (i << 8);               // 0..511
        size_t off = tb + (size_t)(u >> 2)*TILEA_H + (u & 3)*8;
        uint4 w = *(const uint4*)(sq + off);
        float2 f0 = unpack_h2(w.x), f1 = unpack_h2(w.y);
        float2 f2 = unpack_h2(w.z), f3 = unpack_h2(w.w);
        v[i*8+0]=f0.x; v[i*8+1]=f0.y; v[i*8+2]=f1.x; v[i*8+3]=f1.y;
        v[i*8+4]=f2.x; v[i*8+5]=f2.y; v[i*8+6]=f3.x; v[i*8+7]=f3.y;
        mx = fmaxf(mx, fmaxf(fmaxf(fmaxf(f0.x,f0.y),fmaxf(f1.x,f1.y)),
                             fmaxf(fmaxf(f2.x,f2.y),fmaxf(f3.x,f3.y))));
    }
    #pragma unroll
    for (int off = 16; off; off >>= 1)
        mx = fmaxf(mx, __shfl_xor_sync(0xffffffffu, mx, off));
    if ((threadIdx.x & 31) == 0) red[threadIdx.x >> 5] = mx;
    __syncthreads();
    if (threadIdx.x == 0){
        float tv = red[0];
        #pragma unroll
        for (int i = 1; i < 8; i++) tv = fmaxf(tv, red[i]);
        bc = tv;
    }
    __syncthreads();
    mx = bc;

    float sm = 0.f;
    #pragma unroll
    for (int i = 0; i < 16; i++){
        v[i] = __expf(v[i] - mx);
        sm += v[i];
    }
    #pragma unroll
    for (int off = 16; off; off >>= 1)
        sm += __shfl_xor_sync(0xffffffffu, sm, off);
    __syncthreads();
    if ((threadIdx.x & 31) == 0) red[threadIdx.x >> 5] = sm;
    __syncthreads();
    if (threadIdx.x == 0){
        float tv = 0.f;
        #pragma unroll
        for (int i = 0; i < 8; i++) tv += red[i];
        bc = tv;
    }
    __syncthreads();
    const float rinv = 1.f / bc;
    #pragma unroll
    for (int i = 0; i < 2; i++){
        int u = threadIdx.x + (i << 8);
        size_t off = tb + (size_t)(u >> 2)*TILEA_H + (u & 3)*8;
        uint4 w;
        w.x = pack_h2(v[i*8+0]*rinv, v[i*8+1]*rinv);
        w.y = pack_h2(v[i*8+2]*rinv, v[i*8+3]*rinv);
        w.z = pack_h2(v[i*8+4]*rinv, v[i*8+5]*rinv);
        w.w = pack_h2(v[i*8+6]*rinv, v[i*8+7]*rinv);
        *(uint4*)(qh + off) = w;
    }
}

// ---------------------------------------------------------------------------
__global__ void softmax_attn(float* __restrict__ S, __half* __restrict__ at)
{
    __shared__ float red[4];
    __shared__ float bc;
    const int row = blockIdx.x;
    const int b = row >> 9, c = row & 511;
    float* p = S + (size_t)row * 512;
    const size_t tb = (size_t)b*AFMT_AT + (size_t)(c>>7)*16*TILEA_H
                    + (size_t)(c & 127)*A_PAD;

    float v[4];
    float mx = -1e30f;
    #pragma unroll
    for (int i = 0; i < 4; i++){
        int idx = threadIdx.x + (i << 7);
        v[i] = p[idx];
        mx = fmaxf(mx, v[i]);
    }
    #pragma unroll
    for (int off = 16; off; off >>= 1)
        mx = fmaxf(mx, __shfl_xor_sync(0xffffffffu, mx, off));
    if ((threadIdx.x & 31) == 0) red[threadIdx.x >> 5] = mx;
    __syncthreads();
    if (threadIdx.x == 0)
        bc = fmaxf(fmaxf(red[0], red[1]), fmaxf(red[2], red[3]));
    __syncthreads();
    mx = bc;

    float sm = 0.f;
    #pragma unroll
    for (int i = 0; i < 4; i++){
        v[i] = __expf(v[i] - mx);
        sm += v[i];
    }
    #pragma unroll
    for (int off = 16; off; off >>= 1)
        sm += __shfl_xor_sync(0xffffffffu, sm, off);
    __syncthreads();
    if ((threadIdx.x & 31) == 0) red[threadIdx.x >> 5] = sm;
    __syncthreads();
    if (threadIdx.x == 0) bc = red[0] + red[1] + red[2] + red[3];
    __syncthreads();
    const float rinv = 1.f / bc;
    #pragma unroll
    for (int i = 0; i < 4; i++){
        int d = threadIdx.x + (i << 7);
        float f = v[i] * rinv;
        p[d] = f;
        at[tb + (size_t)(d>>5)*TILEA_H + (d & 31)] = __float2half_rn(f);
    }
}

// ---------------------------------------------------------------------------
extern "C" void kernel_launch(void* const* d_in, const int* in_sizes, int n_in,
                              void* d_out, int out_size)
{
    const float* x    = (const float*)d_in[0];
    const float* Wqkv = (const float*)d_in[1];
    const float* bqkv = (const float*)d_in[2];
    const float* Wm   = (const float*)d_in[3];
    const float* bm   = (const float*)d_in[4];
    const float* Wg   = (const float*)d_in[5];
    const float* bg   = (const float*)d_in[6];
    const float* Wr   = (const float*)d_in[7];
    const float* br   = (const float*)d_in[8];

    float* out  = (float*)d_out;
    float* attn = out + (size_t)B_ * C_ * N_;

    cudaFuncSetAttribute(mma_gemm, cudaFuncAttributeMaxDynamicSharedMemorySize, SMEM_TOTAL);

    __half *qkvRM, *vhT, *xhT, *yhT, *sq, *kh, *qh, *at, *gph;
    __half *wqkvT, *wmT, *wgT, *wrT;
    cudaGetSymbolAddress((void**)&qkvRM, g_qkvRM);
    cudaGetSymbolAddress((void**)&vhT,  g_vhT);
    cudaGetSymbolAddress((void**)&xhT,  g_xhT);
    cudaGetSymbolAddress((void**)&yhT,  g_yhT);
    cudaGetSymbolAddress((void**)&sq,   g_sq);
    cudaGetSymbolAddress((void**)&kh,   g_kh);
    cudaGetSymbolAddress((void**)&qh,   g_qh);
    cudaGetSymbolAddress((void**)&at,   g_at);
    cudaGetSymbolAddress((void**)&gph,  g_gph);
    cudaGetSymbolAddress((void**)&wqkvT, g_wqkvT);
    cudaGetSymbolAddress((void**)&wmT,   g_wmT);
    cudaGetSymbolAddress((void**)&wgT,   g_wgT);
    cudaGetSymbolAddress((void**)&wrT,   g_wrT);

    // 0) fused retile
    retile_all<<<(RT_TOTAL + 255)/256, 256>>>(
        Wqkv, wqkvT, Wm, wmT, Wg, wgT, Wr, wrT, x, xhT);

    // 1) qkv (mode 3)
    mma_gemm<<<dim3(32, 12, B_), NTHREADS, SMEM_TOTAL>>>(
        wqkvT, 16, 0,
        xhT, 16, BMN_B, nullptr, 0, 0, 16,
        bqkv, 1.f, nullptr, qkvRM, vhT, nullptr, nullptr,
        16, 1, 3);

    // 2) mqk (mode 2)
    mma_gemm<<<dim3(32, 8, B_), NTHREADS, SMEM_TOTAL>>>(
        wmT, 16, 0,
        vhT, 16, BMN_B, nullptr, 0, 0, 16,
        bm, 1.f, nullptr, sq, kh, qkvRM, nullptr,
        16, 1, 2);

    // 3) softmax_q (coalesced)
    softmax_q<<<NROWS, 256>>>(sq, qh);

    // 4) scores (mode 0, NT, K=4096)
    mma_gemm<<<dim3(4, 4, B_), NTHREADS, SMEM_TOTAL>>>(
        qh, 128, AFMT_BIG,
        kh, 128, AFMT_BIG, nullptr, 0, 0, 128,
        nullptr, 1.0f/sqrtf((float)C_), attn, nullptr, nullptr, nullptr, nullptr,
        128, 0, 0);

    // 5) softmax_attn
    softmax_attn<<<NROWS, 128>>>(attn, at);

    // 6) y (mode 4)
    mma_gemm<<<dim3(32, 4, B_), NTHREADS, SMEM_TOTAL>>>(
        at, 16, AFMT_AT,
        vhT, 16, BMN_B, nullptr, 0, 0, 16,
        nullptr, 1.f, nullptr, yhT, nullptr, nullptr, nullptr,
        16, 1, 4);

    // 7) gate (mode 5)
    mma_gemm<<<dim3(32, 4, B_), NTHREADS, SMEM_TOTAL>>>(
        wgT, 32, 0,
        yhT, 16, BMN_B, xhT, 16, BMN_B, 16,
        bg, 1.f, nullptr, gph, nullptr, nullptr, nullptr,
        32, 1, 5);

    // 8) r + final fuse (mode 1)
    mma_gemm<<<dim3(32, 4, B_), NTHREADS, SMEM_TOTAL>>>(
        wrT, 16, 0,
        xhT, 16, BMN_B, nullptr, 0, 0, 16,
        br, 1.f, out, nullptr, nullptr, gph, yhT,
        16, 1, 1);
}